// round 15
// baseline (speedup 1.0000x reference)
#include <cuda_runtime.h>
#include <cuda_fp16.h>
#include <stdint.h>

#define N_NODES 50000
#define N_EDGES 625000
#define D 128
#define ELLCAP 64
#define MAXOVF 4096
#define NTILES 391              // ceil(N_NODES/128)
#define NPAIRS 74               // 148 CTAs / 2

// ---------------- scratch (no allocs allowed) ----------------
__device__ int   g_deg_out[N_NODES];
__device__ int   g_deg_in[N_NODES];
__device__ int   g_is64;
__device__ __half g_Whi[128 * 256];
__device__ __half g_Wlo[128 * 256];
__device__ __align__(16) __half g_xh[(size_t)N_NODES * D];  // fp16(x)
__device__ __align__(16) int g_ell[(size_t)N_NODES * ELLCAP];
__device__ int   g_ovf_cnt;
__device__ int   g_ovf[2 * MAXOVF];

// ---------------- helpers ----------------
__device__ __forceinline__ uint32_t smem_u32(const void* p) {
    uint32_t a;
    asm("{ .reg .u64 t; cvta.to.shared.u64 t, %1; cvt.u32.u64 %0, t; }" : "=r"(a) : "l"(p));
    return a;
}
__device__ __forceinline__ void ldsm_x4(uint32_t* r, uint32_t addr) {
    asm volatile("ldmatrix.sync.aligned.m8n8.x4.shared.b16 {%0,%1,%2,%3}, [%4];"
                 : "=r"(r[0]), "=r"(r[1]), "=r"(r[2]), "=r"(r[3]) : "r"(addr));
}
__device__ __forceinline__ void cp16(uint32_t dst, const void* src) {
    asm volatile("cp.async.cg.shared.global [%0], [%1], 16;" :: "r"(dst), "l"(src));
}
__device__ __forceinline__ void mma_f16(float* c, const uint32_t* a, const uint32_t* b) {
    asm volatile(
        "mma.sync.aligned.m16n8k16.row.col.f32.f16.f16.f32 "
        "{%0,%1,%2,%3}, {%4,%5,%6,%7}, {%8,%9}, {%0,%1,%2,%3};"
        : "+f"(c[0]), "+f"(c[1]), "+f"(c[2]), "+f"(c[3])
        : "r"(a[0]), "r"(a[1]), "r"(a[2]), "r"(a[3]), "r"(b[0]), "r"(b[1]));
}
__device__ __forceinline__ void bar_sync(int id) {
    asm volatile("bar.sync %0, 512;" :: "r"(id) : "memory");
}
__device__ __forceinline__ void bar_arrive(int id) {
    asm volatile("bar.arrive %0, 512;" :: "r"(id) : "memory");
}
__device__ __forceinline__ int load_idx(const void* p, int e, int is64) {
    return is64 ? (int)((const long long*)p)[e] : ((const int*)p)[e];
}
__device__ __forceinline__ float2 h2f(uint32_t u) {
    return __half22float2(*(__half2*)&u);
}
__device__ __forceinline__ void acc8(float* a, uint4 r, float c) {
    float2 f0 = h2f(r.x), f1 = h2f(r.y), f2 = h2f(r.z), f3 = h2f(r.w);
    a[0] += f0.x * c; a[1] += f0.y * c;
    a[2] += f1.x * c; a[3] += f1.y * c;
    a[4] += f2.x * c; a[5] += f2.y * c;
    a[6] += f3.x * c; a[7] += f3.y * c;
}

// ---------------- K0: zero + probe + W fp16 split ----------------
__global__ void k_init(const void* __restrict__ senders, const float* __restrict__ W) {
    int i = blockIdx.x * blockDim.x + threadIdx.x;
    int stride = gridDim.x * blockDim.x;
    for (int j = i; j < N_NODES; j += stride) { g_deg_out[j] = 0; g_deg_in[j] = 0; }
    for (int j = i; j < 128 * 256; j += stride) {
        float v = W[j];
        __half h = __float2half(v);
        g_Whi[j] = h;
        g_Wlo[j] = __float2half(v - __half2float(h));
    }
    if (i == 0) {
        g_ovf_cnt = 0;
        const int* w = (const int*)senders;
        int is64 = 1;
        #pragma unroll
        for (int k = 0; k < 16; k++) if (w[2 * k + 1] != 0) is64 = 0;
        g_is64 = is64;
    }
}

// ---------------- K1: edges (deg + ELL) + x->fp16 conversion tail ----------------
__global__ void k_ell(const void* __restrict__ senders, const void* __restrict__ receivers,
                      const float* __restrict__ x) {
    int e = blockIdx.x * blockDim.x + threadIdx.x;
    int total = gridDim.x * blockDim.x;
    if (e < N_EDGES) {
        int is64 = g_is64;
        int s = load_idx(senders, e, is64);
        int r = load_idx(receivers, e, is64);
        atomicAdd(&g_deg_in[s], 1);
        int pos = atomicAdd(&g_deg_out[r], 1);
        if (pos < ELLCAP) {
            g_ell[(size_t)r * ELLCAP + pos] = s;
        } else {
            int o = atomicAdd(&g_ovf_cnt, 1);
            if (o < MAXOVF) { g_ovf[2 * o] = r; g_ovf[2 * o + 1] = s; }
        }
    }
    for (int j = e; j < N_NODES * D / 8; j += total) {
        float4 v0 = ((const float4*)x)[j * 2];
        float4 v1 = ((const float4*)x)[j * 2 + 1];
        uint4 p;
        *(__half2*)&p.x = __floats2half2_rn(v0.x, v0.y);
        *(__half2*)&p.y = __floats2half2_rn(v0.z, v0.w);
        *(__half2*)&p.z = __floats2half2_rn(v1.x, v1.y);
        *(__half2*)&p.w = __floats2half2_rn(v1.z, v1.w);
        ((uint4*)g_xh)[j] = p;
    }
}

// ---------------- K2: fused persistent gather+GEMM (warp specialized) ----------------
// 148 CTAs = 74 pairs x 2 N-halves. Warps 0-7: MMA. Warps 8-15: producers
// (cp.async x-half + register-gather agg-half -> smem). Double-buffered A.
#define WP 264
#define AP 264
#define OFF_WHI  0
#define OFF_WLO  (OFF_WHI + 64 * WP * 2)     // 33792
#define OFF_A0   (OFF_WLO + 64 * WP * 2)     // 67584
#define OFF_A1   (OFF_A0 + 128 * AP * 2)     // 135168
#define OFF_BIAS (OFF_A1 + 128 * AP * 2)     // 202752
#define SMEM_K2  (OFF_BIAS + 256)            // 203008
// named barriers: FULL buf0/1 = 1/2, EMPTY buf0/1 = 3/4

__global__ void __launch_bounds__(512, 1)
k_fused(const float* __restrict__ bias, float* __restrict__ out) {
    extern __shared__ char smem[];
    uint32_t sb = smem_u32(smem);
    float* sBias = (float*)(smem + OFF_BIAS);

    int tid = threadIdx.x, wid = tid >> 5, lane = tid & 31;
    int pair = blockIdx.x >> 1;
    int nh   = blockIdx.x & 1;

    // ---- common prologue: W + bias ----
    for (int idx = tid; idx < 2048; idx += 512) {
        int row = idx >> 5;
        int c   = (idx & 31) * 8;
        cp16(sb + OFF_WHI + (uint32_t)((row * WP + c) * 2), g_Whi + (nh * 64 + row) * 256 + c);
        cp16(sb + OFF_WLO + (uint32_t)((row * WP + c) * 2), g_Wlo + (nh * 64 + row) * 256 + c);
    }
    if (tid < 64) sBias[tid] = bias[nh * 64 + tid];
    asm volatile("cp.async.commit_group;");
    asm volatile("cp.async.wait_group 0;");
    __syncthreads();

    if (wid >= 8) {
        // ================= PRODUCER =================
        int ptid = tid - 256;
        int pw   = wid - 8;              // 0..7
        int sl   = lane & 15;
        int nsub = lane >> 4;            // 0/1: which of 2 nodes
        int ovf_cnt = g_ovf_cnt;
        if (ovf_cnt > MAXOVF) ovf_cnt = MAXOVF;

        int t = 0;
        for (int mt = pair; mt < NTILES; mt += NPAIRS, t++) {
            int buf = t & 1;
            uint32_t bufOff = buf ? OFF_A1 : OFF_A0;
            if (t >= 2) bar_sync(3 + buf);           // wait EMPTY

            // x-half via cp.async: 128 rows x 16 chunks
            int nbase = mt * 128;
            for (int idx = ptid; idx < 2048; idx += 256) {
                int row = idx >> 4;
                int c   = idx & 15;
                int n   = nbase + row;
                if (n >= N_NODES) n = 0;
                cp16(sb + bufOff + (uint32_t)((row * AP + c * 8) * 2),
                     g_xh + (size_t)n * D + c * 8);
            }
            asm volatile("cp.async.commit_group;");

            // agg-half: this warp gathers 16 nodes (2 at a time)
            for (int it = 0; it < 8; it++) {
                int row  = pw * 16 + it * 2 + nsub;
                int node = nbase + row;
                if (node < N_NODES) {
                    int deg_full = g_deg_out[node];
                    int deg = deg_full > ELLCAP ? ELLCAP : deg_full;
                    const int4* row4 = (const int4*)(g_ell + (size_t)node * ELLCAP);

                    float a[8];
                    {
                        float ss = rsqrtf((float)(deg_full + 1));
                        uint4 sr = ((const uint4*)(g_xh + (size_t)node * D))[sl];
                        float2 f0 = h2f(sr.x), f1 = h2f(sr.y), f2 = h2f(sr.z), f3 = h2f(sr.w);
                        a[0] = f0.x * ss; a[1] = f0.y * ss;
                        a[2] = f1.x * ss; a[3] = f1.y * ss;
                        a[4] = f2.x * ss; a[5] = f2.y * ss;
                        a[6] = f3.x * ss; a[7] = f3.y * ss;
                    }
                    int j = 0;
                    for (; j + 3 < deg; j += 4) {
                        int4 s4 = row4[j >> 2];
                        int d0 = g_deg_out[s4.x], d1 = g_deg_out[s4.y];
                        int d2 = g_deg_out[s4.z], d3 = g_deg_out[s4.w];
                        uint4 r0 = ((const uint4*)(g_xh + (size_t)s4.x * D))[sl];
                        uint4 r1 = ((const uint4*)(g_xh + (size_t)s4.y * D))[sl];
                        uint4 r2 = ((const uint4*)(g_xh + (size_t)s4.z * D))[sl];
                        uint4 r3 = ((const uint4*)(g_xh + (size_t)s4.w * D))[sl];
                        acc8(a, r0, rsqrtf((float)(d0 + 1)));
                        acc8(a, r1, rsqrtf((float)(d1 + 1)));
                        acc8(a, r2, rsqrtf((float)(d2 + 1)));
                        acc8(a, r3, rsqrtf((float)(d3 + 1)));
                    }
                    for (; j < deg; j++) {
                        int s0 = g_ell[(size_t)node * ELLCAP + j];
                        uint4 rr = ((const uint4*)(g_xh + (size_t)s0 * D))[sl];
                        acc8(a, rr, rsqrtf((float)(g_deg_out[s0] + 1)));
                    }
                    if (deg_full > ELLCAP) {           // overflow fixup (normally never)
                        for (int o = 0; o < ovf_cnt; o++) {
                            if (g_ovf[2 * o] == node) {
                                int s0 = g_ovf[2 * o + 1];
                                uint4 rr = ((const uint4*)(g_xh + (size_t)s0 * D))[sl];
                                acc8(a, rr, rsqrtf((float)(g_deg_out[s0] + 1)));
                            }
                        }
                    }
                    float m = rsqrtf((float)(g_deg_in[node] + 1)) / (float)(deg_full + 1);
                    uint4 pr;
                    *(__half2*)&pr.x = __floats2half2_rn(a[0] * m, a[1] * m);
                    *(__half2*)&pr.y = __floats2half2_rn(a[2] * m, a[3] * m);
                    *(__half2*)&pr.z = __floats2half2_rn(a[4] * m, a[5] * m);
                    *(__half2*)&pr.w = __floats2half2_rn(a[6] * m, a[7] * m);
                    *(uint4*)(smem + bufOff + (row * AP + 128 + sl * 8) * 2) = pr;
                }
            }
            asm volatile("cp.async.wait_group 0;");
            bar_arrive(1 + buf);                      // signal FULL
        }
    } else {
        // ================= CONSUMER =================
        int wm = (wid & 3) * 32;
        int wn = (wid >> 2) * 32;
        int aRow = lane & 15;
        int aCol = (lane >> 4) * 8;
        int bRow = (lane & 7) | ((lane >> 1) & 8);
        int bCol = lane & 8;
        uint32_t aBh = sb + OFF_WHI + (uint32_t)(((wn + bRow) * WP + bCol) * 2);
        uint32_t aBl = sb + OFF_WLO + (uint32_t)(((wn + bRow) * WP + bCol) * 2);
        uint32_t aAbase = (uint32_t)(((wm + aRow) * AP + aCol) * 2);
        int lg = lane >> 2;
        int lk = (lane & 3) * 2;

        int t = 0;
        for (int mt = pair; mt < NTILES; mt += NPAIRS, t++) {
            int buf = t & 1;
            uint32_t bufOff = buf ? OFF_A1 : OFF_A0;
            bar_sync(1 + buf);                        // wait FULL

            uint32_t aA = sb + bufOff + aAbase;
            float acc[2][4][4];
            #pragma unroll
            for (int mi = 0; mi < 2; mi++)
                #pragma unroll
                for (int ni = 0; ni < 4; ni++)
                    #pragma unroll
                    for (int q = 0; q < 4; q++) acc[mi][ni][q] = 0.0f;

            #pragma unroll
            for (int ks = 0; ks < 16; ks++) {
                int kb = ks * 16;
                uint32_t bh[2][4], bl[2][4];
                #pragma unroll
                for (int ng = 0; ng < 2; ng++) {
                    uint32_t off = (uint32_t)((ng * 16 * WP + kb) * 2);
                    ldsm_x4(bh[ng], aBh + off);
                    ldsm_x4(bl[ng], aBl + off);
                }
                #pragma unroll
                for (int mi = 0; mi < 2; mi++) {
                    uint32_t ah[4];
                    ldsm_x4(ah, aA + (uint32_t)((mi * 16 * AP + kb) * 2));
                    #pragma unroll
                    for (int ni = 0; ni < 4; ni++) {
                        const uint32_t* b_hi = &bh[ni >> 1][(ni & 1) * 2];
                        const uint32_t* b_lo = &bl[ni >> 1][(ni & 1) * 2];
                        mma_f16(acc[mi][ni], ah, b_hi);
                        mma_f16(acc[mi][ni], ah, b_lo);
                    }
                }
            }

            // epilogue
            #pragma unroll
            for (int mi = 0; mi < 2; mi++) {
                int r0 = mt * 128 + wm + mi * 16 + lg;
                int r1 = r0 + 8;
                #pragma unroll
                for (int ni = 0; ni < 4; ni++) {
                    int cl = wn + ni * 8 + lk;
                    int col = nh * 64 + cl;
                    float b0 = sBias[cl], b1 = sBias[cl + 1];
                    if (r0 < N_NODES) {
                        float2 v = {acc[mi][ni][0] + b0, acc[mi][ni][1] + b1};
                        *(float2*)(out + (size_t)r0 * D + col) = v;
                    }
                    if (r1 < N_NODES) {
                        float2 v = {acc[mi][ni][2] + b0, acc[mi][ni][3] + b1};
                        *(float2*)(out + (size_t)r1 * D + col) = v;
                    }
                }
            }
            bar_arrive(3 + buf);                      // signal EMPTY
        }
    }
}

// ---------------- launch ----------------
extern "C" void kernel_launch(void* const* d_in, const int* in_sizes, int n_in,
                              void* d_out, int out_size) {
    const float* x   = (const float*)d_in[0];
    const void*  snd = d_in[1];
    const void*  rcv = d_in[2];
    const float* W   = nullptr;
    const float* b   = nullptr;
    for (int i = 3; i < n_in; i++) {
        if (in_sizes[i] == 2 * D * D) W = (const float*)d_in[i];
        else if (in_sizes[i] == D)    b = (const float*)d_in[i];
    }
    float* out = (float*)d_out;

    k_init<<<148, 256>>>(snd, W);
    k_ell<<<(N_EDGES + 255) / 256, 256>>>(snd, rcv, x);

    cudaFuncSetAttribute(k_fused, cudaFuncAttributeMaxDynamicSharedMemorySize, SMEM_K2);
    k_fused<<<2 * NPAIRS, 512, SMEM_K2>>>(b, out);
}

// round 16
// speedup vs baseline: 2.5086x; 2.5086x over previous
#include <cuda_runtime.h>
#include <cuda_fp16.h>
#include <stdint.h>

#define N_NODES 50000
#define N_EDGES 625000
#define D 128
#define ELLCAP 64
#define MAXOVF 4096
#define NTILES 391              // ceil(N_NODES/128)
#define NPAIRS 74               // 148 CTAs / 2

// ---------------- scratch (no allocs allowed) ----------------
// g_deg: [0,N)=deg_out, [N,2N)=deg_in, [2N]=ovf_cnt, [2N+1]=done  (one memset)
__device__ int   g_deg[2 * N_NODES + 2];
__device__ __half g_Wh[128 * 256];                   // fp16(W), row-major [N][K]
__device__ __align__(16) __half g_xh[(size_t)N_NODES * D];  // fp16(x)
__device__ __align__(16) __half g_ah[(size_t)N_NODES * D];  // fp16(agg*mscale)
__device__ __align__(16) int g_ell[(size_t)N_NODES * ELLCAP];
__device__ int   g_ovf[2 * MAXOVF];

// ---------------- helpers ----------------
__device__ __forceinline__ uint32_t smem_u32(const void* p) {
    uint32_t a;
    asm("{ .reg .u64 t; cvta.to.shared.u64 t, %1; cvt.u32.u64 %0, t; }" : "=r"(a) : "l"(p));
    return a;
}
__device__ __forceinline__ void ldsm_x4(uint32_t* r, uint32_t addr) {
    asm volatile("ldmatrix.sync.aligned.m8n8.x4.shared.b16 {%0,%1,%2,%3}, [%4];"
                 : "=r"(r[0]), "=r"(r[1]), "=r"(r[2]), "=r"(r[3]) : "r"(addr));
}
__device__ __forceinline__ void cp16(uint32_t dst, const void* src) {
    asm volatile("cp.async.cg.shared.global [%0], [%1], 16;" :: "r"(dst), "l"(src));
}
__device__ __forceinline__ void mma_f16(float* c, const uint32_t* a, const uint32_t* b) {
    asm volatile(
        "mma.sync.aligned.m16n8k16.row.col.f32.f16.f16.f32 "
        "{%0,%1,%2,%3}, {%4,%5,%6,%7}, {%8,%9}, {%0,%1,%2,%3};"
        : "+f"(c[0]), "+f"(c[1]), "+f"(c[2]), "+f"(c[3])
        : "r"(a[0]), "r"(a[1]), "r"(a[2]), "r"(a[3]), "r"(b[0]), "r"(b[1]));
}
__device__ __forceinline__ int load_idx(const void* p, int e, int is64) {
    return is64 ? (int)((const long long*)p)[e] : ((const int*)p)[e];
}
__device__ __forceinline__ float2 h2f(uint32_t u) {
    return __half22float2(*(__half2*)&u);
}
__device__ __forceinline__ void acc8(float* a, uint4 r, float c) {
    float2 f0 = h2f(r.x), f1 = h2f(r.y), f2 = h2f(r.z), f3 = h2f(r.w);
    a[0] += f0.x * c; a[1] += f0.y * c;
    a[2] += f1.x * c; a[3] += f1.y * c;
    a[4] += f2.x * c; a[5] += f2.y * c;
    a[6] += f3.x * c; a[7] += f3.y * c;
}

// ---------------- K1: edges (deg + ELL) + W/x fp16 conversion tails ----------------
__global__ void k_ell(const void* __restrict__ senders, const void* __restrict__ receivers,
                      const float* __restrict__ x, const float* __restrict__ W) {
    __shared__ int s_is64;
    if (threadIdx.x == 0) {
        const int* w = (const int*)senders;
        int is64 = 1;
        #pragma unroll
        for (int k = 0; k < 16; k++) if (w[2 * k + 1] != 0) is64 = 0;
        s_is64 = is64;
    }
    __syncthreads();
    int is64 = s_is64;

    int e = blockIdx.x * blockDim.x + threadIdx.x;
    int total = gridDim.x * blockDim.x;
    if (e < N_EDGES) {
        int s = load_idx(senders, e, is64);
        int r = load_idx(receivers, e, is64);
        atomicAdd(&g_deg[N_NODES + s], 1);
        int pos = atomicAdd(&g_deg[r], 1);       // deg_out == ELL cursor
        if (pos < ELLCAP) {
            g_ell[(size_t)r * ELLCAP + pos] = s;
        } else {
            int o = atomicAdd(&g_deg[2 * N_NODES], 1);
            if (o < MAXOVF) { g_ovf[2 * o] = r; g_ovf[2 * o + 1] = s; }
        }
    }
    // W -> fp16 (single term)
    for (int j = e; j < 128 * 256; j += total) g_Wh[j] = __float2half(W[j]);
    // x -> fp16 (8 floats/iter), overlapped with atomic latency above
    for (int j = e; j < N_NODES * D / 8; j += total) {
        float4 v0 = ((const float4*)x)[j * 2];
        float4 v1 = ((const float4*)x)[j * 2 + 1];
        uint4 p;
        *(__half2*)&p.x = __floats2half2_rn(v0.x, v0.y);
        *(__half2*)&p.y = __floats2half2_rn(v0.z, v0.w);
        *(__half2*)&p.z = __floats2half2_rn(v1.x, v1.y);
        *(__half2*)&p.w = __floats2half2_rn(v1.z, v1.w);
        ((uint4*)g_xh)[j] = p;
    }
}

// ---------------- K2: gather (2 nodes/warp, 16 lanes/node, 8-deep MLP) ----------------
__global__ void __launch_bounds__(256) k_gather() {
    __shared__ int sdone;
    int gid  = blockIdx.x * blockDim.x + threadIdx.x;
    int lane = threadIdx.x & 31;
    int node = (gid >> 5) * 2 + (lane >> 4);    // 2 nodes per warp
    int sl   = lane & 15;                        // 16B lane within 256B row

    if (node < N_NODES) {
        int deg_full = g_deg[node];
        int deg = deg_full > ELLCAP ? ELLCAP : deg_full;
        const int4* row4 = (const int4*)(g_ell + (size_t)node * ELLCAP);

        float a[8];
        {
            float ss = rsqrtf((float)(deg_full + 1));
            uint4 sr = ((const uint4*)(g_xh + (size_t)node * D))[sl];
            float2 f0 = h2f(sr.x), f1 = h2f(sr.y), f2 = h2f(sr.z), f3 = h2f(sr.w);
            a[0] = f0.x * ss; a[1] = f0.y * ss;
            a[2] = f1.x * ss; a[3] = f1.y * ss;
            a[4] = f2.x * ss; a[5] = f2.y * ss;
            a[6] = f3.x * ss; a[7] = f3.y * ss;
        }

        int j = 0;
        for (; j + 3 < deg; j += 4) {
            int4 s4 = row4[j >> 2];
            int d0 = g_deg[s4.x], d1 = g_deg[s4.y];
            int d2 = g_deg[s4.z], d3 = g_deg[s4.w];
            uint4 r0 = ((const uint4*)(g_xh + (size_t)s4.x * D))[sl];
            uint4 r1 = ((const uint4*)(g_xh + (size_t)s4.y * D))[sl];
            uint4 r2 = ((const uint4*)(g_xh + (size_t)s4.z * D))[sl];
            uint4 r3 = ((const uint4*)(g_xh + (size_t)s4.w * D))[sl];
            acc8(a, r0, rsqrtf((float)(d0 + 1)));
            acc8(a, r1, rsqrtf((float)(d1 + 1)));
            acc8(a, r2, rsqrtf((float)(d2 + 1)));
            acc8(a, r3, rsqrtf((float)(d3 + 1)));
        }
        for (; j < deg; j++) {
            int s0 = g_ell[(size_t)node * ELLCAP + j];
            uint4 rr = ((const uint4*)(g_xh + (size_t)s0 * D))[sl];
            acc8(a, rr, rsqrtf((float)(g_deg[s0] + 1)));
        }

        float m = rsqrtf((float)(g_deg[N_NODES + node] + 1)) / (float)(deg_full + 1);
        uint4 pr;
        *(__half2*)&pr.x = __floats2half2_rn(a[0] * m, a[1] * m);
        *(__half2*)&pr.y = __floats2half2_rn(a[2] * m, a[3] * m);
        *(__half2*)&pr.z = __floats2half2_rn(a[4] * m, a[5] * m);
        *(__half2*)&pr.w = __floats2half2_rn(a[6] * m, a[7] * m);
        ((uint4*)(g_ah + (size_t)node * D))[sl] = pr;
    }

    // ---- last-done block: sequential overflow fixup (normally empty) ----
    __syncthreads();
    if (threadIdx.x == 0) {
        __threadfence();
        int t = atomicAdd(&g_deg[2 * N_NODES + 1], 1);
        sdone = (t == (int)gridDim.x - 1) ? 1 : 0;
    }
    __syncthreads();
    if (sdone && (threadIdx.x >> 5) == 0) {
        int cnt = g_deg[2 * N_NODES];
        if (cnt > MAXOVF) cnt = MAXOVF;
        for (int o = 0; o < cnt; o++) {          // sequential: no r-races
            int r = g_ovf[2 * o], s = g_ovf[2 * o + 1];
            float cs = rsqrtf((float)(g_deg[s] + 1));
            float m  = rsqrtf((float)(g_deg[N_NODES + r] + 1)) / (float)(g_deg[r] + 1);
            float f = cs * m;
            uint2 xr = ((const uint2*)(g_xh + (size_t)s * D))[lane];
            uint2 ar = ((const uint2*)(g_ah + (size_t)r * D))[lane];
            float2 xa = h2f(xr.x), xb = h2f(xr.y);
            float2 aa = h2f(ar.x), ab = h2f(ar.y);
            aa.x += xa.x * f; aa.y += xa.y * f;
            ab.x += xb.x * f; ab.y += xb.y * f;
            uint2 pr;
            *(__half2*)&pr.x = __floats2half2_rn(aa.x, aa.y);
            *(__half2*)&pr.y = __floats2half2_rn(ab.x, ab.y);
            ((uint2*)(g_ah + (size_t)r * D))[lane] = pr;
            __syncwarp();
        }
    }
}

// ---------------- K3: persistent fp16 GEMM (single W term) ----------------
#define WP 264
#define AP 264
#define OFF_WH   0
#define OFF_A0   (OFF_WH + 64 * WP * 2)      // 33792
#define OFF_A1   (OFF_A0 + 128 * AP * 2)     // 101376
#define OFF_BIAS (OFF_A1 + 128 * AP * 2)     // 168960
#define SMEM_K3  (OFF_BIAS + 256)            // 169216

__device__ __forceinline__ void fillA(uint32_t sb, uint32_t bufOff, int mt, int tid) {
    int nbase = mt * 128;
    for (int idx = tid; idx < 4096; idx += 512) {
        int row = idx >> 5;
        int c   = idx & 31;
        int n   = nbase + row;
        if (n >= N_NODES) n = 0;
        const void* src = (c < 16)
            ? (const void*)(g_xh + (size_t)n * D + c * 8)
            : (const void*)(g_ah + (size_t)n * D + (c - 16) * 8);
        cp16(sb + bufOff + (uint32_t)((row * AP + c * 8) * 2), src);
    }
}

__global__ void __launch_bounds__(512, 1)
k_gemm_mma(const float* __restrict__ bias, float* __restrict__ out) {
    extern __shared__ char smem[];
    uint32_t sb = smem_u32(smem);
    float* sBias = (float*)(smem + OFF_BIAS);

    int tid = threadIdx.x, wid = tid >> 5, lane = tid & 31;
    int pair = blockIdx.x >> 1;
    int nh   = blockIdx.x & 1;

    for (int idx = tid; idx < 2048; idx += 512) {
        int row = idx >> 5;
        int c   = (idx & 31) * 8;
        cp16(sb + OFF_WH + (uint32_t)((row * WP + c) * 2), g_Wh + (nh * 64 + row) * 256 + c);
    }
    if (tid < 64) sBias[tid] = bias[nh * 64 + tid];
    if (pair < NTILES) fillA(sb, OFF_A0, pair, tid);
    asm volatile("cp.async.commit_group;");
    asm volatile("cp.async.wait_group 0;");
    __syncthreads();

    int wm  = (wid & 3) * 32;
    int wnl = (wid >> 2) * 16;
    int aRow = lane & 15;
    int aCol = (lane >> 4) * 8;
    int bRow = (lane & 7) | ((lane >> 1) & 8);
    int bCol = lane & 8;
    uint32_t aBh = sb + OFF_WH + (uint32_t)(((wnl + bRow) * WP + bCol) * 2);
    uint32_t aAbase = (uint32_t)(((wm + aRow) * AP + aCol) * 2);

    int t = 0;
    for (int mt = pair; mt < NTILES; mt += NPAIRS, t++) {
        uint32_t curOff = (t & 1) ? OFF_A1 : OFF_A0;
        uint32_t nxtOff = (t & 1) ? OFF_A0 : OFF_A1;
        int mtn = mt + NPAIRS;
        if (mtn < NTILES) fillA(sb, nxtOff, mtn, tid);
        asm volatile("cp.async.commit_group;");

        uint32_t aA = sb + curOff + aAbase;
        float acc[2][2][4];
        #pragma unroll
        for (int mi = 0; mi < 2; mi++)
            #pragma unroll
            for (int ni = 0; ni < 2; ni++)
                #pragma unroll
                for (int q = 0; q < 4; q++) acc[mi][ni][q] = 0.0f;

        #pragma unroll
        for (int ks = 0; ks < 16; ks++) {
            int kb = ks * 16;
            uint32_t bh[4];
            ldsm_x4(bh, aBh + (uint32_t)(kb * 2));
            #pragma unroll
            for (int mi = 0; mi < 2; mi++) {
                uint32_t ah[4];
                ldsm_x4(ah, aA + (uint32_t)((mi * 16 * AP + kb) * 2));
                mma_f16(acc[mi][0], ah, &bh[0]);
                mma_f16(acc[mi][1], ah, &bh[2]);
            }
        }

        int lg = lane >> 2;
        int lk = (lane & 3) * 2;
        #pragma unroll
        for (int mi = 0; mi < 2; mi++) {
            int r0 = mt * 128 + wm + mi * 16 + lg;
            int r1 = r0 + 8;
            #pragma unroll
            for (int ni = 0; ni < 2; ni++) {
                int cl = wnl + ni * 8 + lk;
                int col = nh * 64 + cl;
                float b0 = sBias[cl], b1 = sBias[cl + 1];
                if (r0 < N_NODES) {
                    float2 v = {acc[mi][ni][0] + b0, acc[mi][ni][1] + b1};
                    *(float2*)(out + (size_t)r0 * D + col) = v;
                }
                if (r1 < N_NODES) {
                    float2 v = {acc[mi][ni][2] + b0, acc[mi][ni][3] + b1};
                    *(float2*)(out + (size_t)r1 * D + col) = v;
                }
            }
        }

        asm volatile("cp.async.wait_group 0;");
        __syncthreads();
    }
}

// ---------------- launch ----------------
extern "C" void kernel_launch(void* const* d_in, const int* in_sizes, int n_in,
                              void* d_out, int out_size) {
    const float* x   = (const float*)d_in[0];
    const void*  snd = d_in[1];
    const void*  rcv = d_in[2];
    const float* W   = nullptr;
    const float* b   = nullptr;
    for (int i = 3; i < n_in; i++) {
        if (in_sizes[i] == 2 * D * D) W = (const float*)d_in[i];
        else if (in_sizes[i] == D)    b = (const float*)d_in[i];
    }
    float* out = (float*)d_out;

    void* p_deg = nullptr;
    cudaGetSymbolAddress(&p_deg, g_deg);
    cudaMemsetAsync(p_deg, 0, sizeof(int) * (2 * N_NODES + 2));

    k_ell<<<(N_EDGES + 255) / 256, 256>>>(snd, rcv, x, W);
    k_gather<<<(N_NODES / 2 * 32 + 255) / 256, 256>>>();

    cudaFuncSetAttribute(k_gemm_mma, cudaFuncAttributeMaxDynamicSharedMemorySize, SMEM_K3);
    k_gemm_mma<<<2 * NPAIRS, 512, SMEM_K3>>>(b, out);
}